// round 16
// baseline (speedup 1.0000x reference)
#include <cuda_runtime.h>
#include <cuda_fp16.h>
#include <cuda_pipeline.h>
#include <mma.h>
#include <cstdint>

using namespace nvcuda;

#define NN 100000
#define NE 1600000
#define DD 128
#define KK 256   // concat K: [mean | h]

// ---------------- static device scratch (~51MB) ---------------------------------
__device__ __half g_x0[(size_t)NN * DD];    // fp16 activations, ping
__device__ __half g_x1[(size_t)NN * DD];    // fp16 activations, pong
__device__ __half g_W[3 * KK * DD];         // fp16 concat weights [Wl ; Wr+I]
// CSR (g_cnt statically zero-initialized; scan_kernel re-zeros it each launch)
__device__ int g_cnt[NN];
__device__ int g_rowptr[NN + 1];
__device__ int g_cursor[NN];
__device__ int g_csrc[NE];

// ---------------- helpers ----------------
__device__ __forceinline__ float4 ld_h4(const __half* X, size_t off) {
    uint2 u = *reinterpret_cast<const uint2*>(X + off);
    float2 f01 = __half22float2(*reinterpret_cast<__half2*>(&u.x));
    float2 f23 = __half22float2(*reinterpret_cast<__half2*>(&u.y));
    return make_float4(f01.x, f01.y, f23.x, f23.y);
}

__device__ __forceinline__ uint2 f4_to_h4(const float4 v) {
    __half2 h01 = __floats2half2_rn(v.x, v.y);
    __half2 h23 = __floats2half2_rn(v.z, v.w);
    uint2 u;
    u.x = *reinterpret_cast<unsigned*>(&h01);
    u.y = *reinterpret_cast<unsigned*>(&h23);
    return u;
}

// ---------------- conversion: weights (+I fold) and x -> fp16 set 0 -------------
__global__ void convert_all_kernel(const float* __restrict__ Wl,
                                   const float* __restrict__ Wr,
                                   const float* __restrict__ x) {
    int idx = blockIdx.x * blockDim.x + threadIdx.x;
    const int nw = 3 * KK * DD;
    if (idx < nw) {
        int l = idx / (KK * DD);
        int r = idx - l * (KK * DD);
        int k = r / DD;
        int n = r - k * DD;
        float v;
        if (k < DD) {
            v = Wl[(size_t)l * DD * DD + k * DD + n];
        } else {
            v = Wr[(size_t)l * DD * DD + (k - DD) * DD + n];
            if (k - DD == n) v += 1.0f;       // fold residual: h @ (Wr + I)
        }
        g_W[idx] = __float2half_rn(v);
    }
    size_t n4 = (size_t)NN * DD / 4;
    size_t stride = (size_t)gridDim.x * blockDim.x;
    for (size_t v = (size_t)idx; v < n4; v += stride) {
        float4 f = reinterpret_cast<const float4*>(x)[v];
        reinterpret_cast<uint2*>(g_x0)[v] = f4_to_h4(f);
    }
}

// ---------------- CSR build ----------------
__global__ void hist_kernel(const int* __restrict__ dst) {
    int stride = gridDim.x * blockDim.x;
    for (int e = blockIdx.x * blockDim.x + threadIdx.x; e < NE; e += stride)
        atomicAdd(&g_cnt[dst[e]], 1);
}

__global__ void scan_kernel() {
    __shared__ int sh[1024];
    const int t = threadIdx.x;
    const int chunk = (NN + 1023) / 1024;
    int start = t * chunk;
    int end   = min(start + chunk, NN);
    int s = 0;
    for (int j = start; j < end; j++) {
        g_rowptr[j] = s;
        s += g_cnt[j];
        g_cnt[j] = 0;        // restore for next launch
    }
    sh[t] = s;
    __syncthreads();
    for (int off = 1; off < 1024; off <<= 1) {
        int v = (t >= off) ? sh[t - off] : 0;
        __syncthreads();
        sh[t] += v;
        __syncthreads();
    }
    int excl = (t == 0) ? 0 : sh[t - 1];
    for (int j = start; j < end; j++) {
        int v = g_rowptr[j] + excl;
        g_rowptr[j] = v;
        g_cursor[j] = v;
    }
    if (t == 0) g_rowptr[NN] = NE;
}

__global__ void fill_kernel(const int* __restrict__ src, const int* __restrict__ dst) {
    int stride = gridDim.x * blockDim.x;
    for (int e = blockIdx.x * blockDim.x + threadIdx.x; e < NE; e += stride) {
        int p = atomicAdd(&g_cursor[dst[e]], 1);
        g_csrc[p] = src[e];
    }
}

// ---------------- fused gather + fp16 tensor-core GEMM -------------------------
// Per block: compute 128 row-means into resident smem (A cols 0..127), then
// out = [mean | h] @ [Wl ; Wr+I] + b with x-half + weights streamed (cp.async).
#define MLD 136
#define MEAN_BYTES (128 * MLD * 2)            // 34816
#define ALD 40
#define BLD 136
#define ST_X_BYTES (128 * ALD * 2)            // 10240
#define ST_B_BYTES (32 * BLD * 2)             // 8704
#define STAGE_BYTES (ST_X_BYTES + ST_B_BYTES) // 18944
#define SM_TOT (MEAN_BYTES + 2 * STAGE_BYTES) // 72704
#define STG_LD 132

__global__ __launch_bounds__(256, 2)
void sage_fused_kernel(float* __restrict__ oout,
                       const float* __restrict__ bias,
                       int lw, int rsel, int wsel, int do_relu, int f32out) {
    const __half* __restrict__ X = rsel ? g_x1 : g_x0;
    __half* __restrict__ WX = (wsel == 1) ? g_x1 : g_x0;

    extern __shared__ __align__(16) char smem[];
    __half* Am = reinterpret_cast<__half*>(smem);            // mean [128][MLD]
    char*   stg = smem + MEAN_BYTES;                          // 2 pipeline stages
    float*  stage = reinterpret_cast<float*>(stg);            // epilogue alias

    const int tid = threadIdx.x;
    const int w  = tid >> 5;
    const int lane = tid & 31;
    const int wm = w >> 2;              // 0..1 : 64-row group
    const int wn = w & 3;               // 0..3 : 32-col group
    const int rowBase = blockIdx.x * 128;

    // x copy: row = tid>>1 (0..127), 16 halves per thread (2 x 16B)
    const int ar = tid >> 1;
    const int ac = (tid & 1) * 16;
    const int aclamp = min(rowBase + ar, NN - 1);
    // B copy: kr = tid>>3 (0..31), 16 halves per thread (2 x 16B)
    const int bkr = tid >> 3;
    const int bnc = (tid & 7) * 16;

    auto copy_stage = [&](int kb, int b) {
        char* base = stg + b * STAGE_BYTES;
        __half* As = reinterpret_cast<__half*>(base);
        __half* Bs = reinterpret_cast<__half*>(base + ST_X_BYTES);
        if (kb >= 4) {                   // x-half of A (K 128..255)
            int k0 = (kb & 3) * 32;
            #pragma unroll
            for (int q = 0; q < 2; q++)
                __pipeline_memcpy_async(As + ar * ALD + ac + q * 8,
                                        X + (size_t)aclamp * DD + k0 + ac + q * 8, 16);
        }
        #pragma unroll
        for (int q = 0; q < 2; q++)
            __pipeline_memcpy_async(Bs + bkr * BLD + bnc + q * 8,
                                    g_W + (size_t)lw + (size_t)(kb * 32 + bkr) * DD
                                        + bnc + q * 8, 16);
    };

    // issue weight stage 0 BEFORE gather so copies overlap gather compute
    copy_stage(0, 0);
    __pipeline_commit();

    // ---- gather phase: warp w computes means for rows w*16 .. w*16+15 ----
    for (int rr = 0; rr < 16; rr++) {
        int row = w * 16 + rr;
        int n = rowBase + row;
        float4 a0 = make_float4(0.f, 0.f, 0.f, 0.f);
        float4 a1 = a0, a2 = a0, a3 = a0;
        if (n < NN) {
            int beg = g_rowptr[n];
            int end = g_rowptr[n + 1];
            int e = beg;
            for (; e + 4 <= end; e += 4) {
                int s0 = __ldg(&g_csrc[e + 0]);
                int s1 = __ldg(&g_csrc[e + 1]);
                int s2 = __ldg(&g_csrc[e + 2]);
                int s3 = __ldg(&g_csrc[e + 3]);
                float4 v0 = ld_h4(X, (size_t)s0 * DD + lane * 4);
                float4 v1 = ld_h4(X, (size_t)s1 * DD + lane * 4);
                float4 v2 = ld_h4(X, (size_t)s2 * DD + lane * 4);
                float4 v3 = ld_h4(X, (size_t)s3 * DD + lane * 4);
                a0.x += v0.x; a0.y += v0.y; a0.z += v0.z; a0.w += v0.w;
                a1.x += v1.x; a1.y += v1.y; a1.z += v1.z; a1.w += v1.w;
                a2.x += v2.x; a2.y += v2.y; a2.z += v2.z; a2.w += v2.w;
                a3.x += v3.x; a3.y += v3.y; a3.z += v3.z; a3.w += v3.w;
            }
            for (; e < end; e++) {
                int s = __ldg(&g_csrc[e]);
                float4 v = ld_h4(X, (size_t)s * DD + lane * 4);
                a0.x += v.x; a0.y += v.y; a0.z += v.z; a0.w += v.w;
            }
            float invd = 1.f / fmaxf((float)(end - beg), 1.f);
            a0.x = (a0.x + a1.x + a2.x + a3.x) * invd;
            a0.y = (a0.y + a1.y + a2.y + a3.y) * invd;
            a0.z = (a0.z + a1.z + a2.z + a3.z) * invd;
            a0.w = (a0.w + a1.w + a2.w + a3.w) * invd;
        }
        *reinterpret_cast<uint2*>(Am + row * MLD + lane * 4) = f4_to_h4(a0);
    }

    wmma::fragment<wmma::accumulator, 16, 16, 16, float> acc[4][2];
    #pragma unroll
    for (int i = 0; i < 4; i++)
        #pragma unroll
        for (int j = 0; j < 2; j++) wmma::fill_fragment(acc[i][j], 0.f);

    // ---- MMA phase: 8 stages of BK=32 ----
    for (int kb = 0; kb < 8; kb++) {
        if (kb < 7) {
            copy_stage(kb + 1, (kb + 1) & 1);   // issue next BEFORE waiting
            __pipeline_commit();
            __pipeline_wait_prior(1);
        } else {
            __pipeline_wait_prior(0);
        }
        __syncthreads();   // stage landed + (kb==0) mean smem ready

        char* base = stg + (kb & 1) * STAGE_BYTES;
        __half* As = reinterpret_cast<__half*>(base);
        __half* Bs = reinterpret_cast<__half*>(base + ST_X_BYTES);
        const bool useMean = (kb < 4);
        const __half* Asrc = useMean ? (Am + (kb & 3) * 32) : As;
        const int lda = useMean ? MLD : ALD;

        #pragma unroll
        for (int kk = 0; kk < 32; kk += 16) {
            wmma::fragment<wmma::matrix_b, 16, 16, 16, __half, wmma::row_major> bf[2];
            #pragma unroll
            for (int j = 0; j < 2; j++)
                wmma::load_matrix_sync(bf[j], Bs + kk * BLD + wn * 32 + j * 16, BLD);
            #pragma unroll
            for (int i = 0; i < 4; i++) {
                wmma::fragment<wmma::matrix_a, 16, 16, 16, __half, wmma::row_major> af;
                wmma::load_matrix_sync(af, Asrc + (wm * 64 + i * 16) * lda + kk, lda);
                #pragma unroll
                for (int j = 0; j < 2; j++)
                    wmma::mma_sync(acc[i][j], af, bf[j], acc[i][j]);
            }
        }
        __syncthreads();
    }

    // ---- epilogue in two 64-row halves (stage aliases the pipeline smem) ----
    #pragma unroll
    for (int ph = 0; ph < 2; ph++) {
        if (wm == ph) {
            #pragma unroll
            for (int i = 0; i < 4; i++)
                #pragma unroll
                for (int j = 0; j < 2; j++)
                    wmma::store_matrix_sync(stage + (i * 16) * STG_LD + wn * 32 + j * 16,
                                            acc[i][j], STG_LD, wmma::mem_row_major);
        }
        __syncthreads();
        #pragma unroll
        for (int it = 0; it < 8; it++) {
            int idx = it * 256 + tid;          // 0..2047
            int row = idx >> 5;                // 0..63
            int c4  = (idx & 31) * 4;          // 0..124
            int grow = rowBase + ph * 64 + row;
            if (grow < NN) {
                const float* sp = stage + row * STG_LD + c4;
                float4 bb = *reinterpret_cast<const float4*>(bias + c4);
                float4 o;
                o.x = sp[0] + bb.x;
                o.y = sp[1] + bb.y;
                o.z = sp[2] + bb.z;
                o.w = sp[3] + bb.w;
                if (do_relu) {
                    o.x = fmaxf(o.x, 0.f); o.y = fmaxf(o.y, 0.f);
                    o.z = fmaxf(o.z, 0.f); o.w = fmaxf(o.w, 0.f);
                }
                if (f32out)
                    *reinterpret_cast<float4*>(oout + (size_t)grow * DD + c4) = o;
                if (wsel >= 0)
                    reinterpret_cast<uint2*>(WX)[((size_t)grow * DD + c4) / 4] =
                        f4_to_h4(o);
            }
        }
        __syncthreads();
    }
}

// ---------------- launch ----------------
extern "C" void kernel_launch(void* const* d_in, const int* in_sizes, int n_in,
                              void* d_out, int out_size) {
    const float* x  = (const float*)d_in[0];
    const int*   ei = (const int*)d_in[1];
    const float* Wl = (const float*)d_in[2];
    const float* bl = (const float*)d_in[3];
    const float* Wr = (const float*)d_in[4];
    const int* src = ei;
    const int* dst = ei + NE;
    float* out = (float*)d_out;

    const int SB = 1184;
    const int GB = (NN + 127) / 128;             // 782 fused blocks

    // opt into >48KB dynamic smem (idempotent; non-enqueuing host call)
    cudaFuncSetAttribute(sage_fused_kernel,
                         cudaFuncAttributeMaxDynamicSharedMemorySize, SM_TOT);

    convert_all_kernel<<<SB, 256>>>(Wl, Wr, x);  // launch 1
    hist_kernel<<<SB, 256>>>(dst);               // launch 2
    scan_kernel<<<1, 1024>>>();                  // launch 3
    fill_kernel<<<SB, 256>>>(src, dst);          // launch 4

    // layer 0: reads x0, writes x1 (relu)
    sage_fused_kernel<<<GB, 256, SM_TOT>>>(out, bl, 0 * KK * DD, 0, 1, 1, 0);
    // layer 1: reads x1, writes x0 (relu)
    sage_fused_kernel<<<GB, 256, SM_TOT>>>(out, bl + DD, 1 * KK * DD, 1, 0, 1, 0);
    // layer 2: reads x0, writes f32 out only (no relu)
    sage_fused_kernel<<<GB, 256, SM_TOT>>>(out, bl + 2 * DD, 2 * KK * DD, 0, -1, 0, 1);
}